// round 2
// baseline (speedup 1.0000x reference)
#include <cuda_runtime.h>

// Problem constants
#define B_ 8
#define N_ 2048
#define F_ 128
#define M_ (B_*N_)          // 16384 total rows
#define LAYERS_ 2
#define NSPLIT_ 16          // split-K for S reduction
#define SLOPE_ 0.1f
#define INV_NM1_ (1.0f/2047.0f)

// Scratch (device globals; no cudaMalloc allowed)
__device__ float g_w1[M_*F_];
__device__ float g_w2[M_*F_];
__device__ float g_msg[M_*F_];
__device__ float g_Spart[B_*NSPLIT_*F_*F_];
__device__ float g_S[B_*F_*F_];

__device__ __forceinline__ float lrelu(float v) { return v >= 0.f ? v : SLOPE_*v; }

// ---------------------------------------------------------------------------
// Y[M,128] = lrelu(X[M,128] @ W[128,128] + bias) (+ R optionally)
// Block: 128-row tile, 256 threads, 8x8 register tile per thread, K chunked x32.
// ---------------------------------------------------------------------------
template<bool ACT, bool RES>
__global__ void __launch_bounds__(256) gemm128(
    const float* __restrict__ X, const float* __restrict__ W,
    const float* __restrict__ bias, const float* __restrict__ R,
    float* __restrict__ Y)
{
    __shared__ float Xs[128][33];   // [row][k] padded (k-chunk of 32)
    __shared__ float Ws[32][128];   // [k][col]

    const int row0 = blockIdx.x * 128;
    const int tid  = threadIdx.x;
    const int tx   = tid & 15;      // col group (8 cols)
    const int ty   = tid >> 4;      // row group (8 rows)

    float acc[8][8];
    #pragma unroll
    for (int i = 0; i < 8; ++i)
        #pragma unroll
        for (int j = 0; j < 8; ++j) acc[i][j] = 0.f;

    for (int c = 0; c < 4; ++c) {
        // Load X chunk: 128 rows x 32 k  (1024 float4)
        #pragma unroll
        for (int i = 0; i < 4; ++i) {
            int f4 = tid + i*256;
            int r  = f4 >> 3;             // /8   (8 float4 per row)
            int kq = (f4 & 7) << 2;       // *4
            float4 v = *(const float4*)&X[(size_t)(row0 + r)*F_ + c*32 + kq];
            Xs[r][kq+0] = v.x; Xs[r][kq+1] = v.y; Xs[r][kq+2] = v.z; Xs[r][kq+3] = v.w;
        }
        // Load W chunk: 32 k x 128 cols (1024 float4)
        #pragma unroll
        for (int i = 0; i < 4; ++i) {
            int f4 = tid + i*256;
            int r  = f4 >> 5;             // /32
            int q  = (f4 & 31) << 2;
            *(float4*)&Ws[r][q] = *(const float4*)&W[(size_t)(c*32 + r)*F_ + q];
        }
        __syncthreads();

        #pragma unroll
        for (int k = 0; k < 32; ++k) {
            float a[8], b[8];
            #pragma unroll
            for (int i = 0; i < 8; ++i) a[i] = Xs[ty*8 + i][k];
            *(float4*)&b[0] = *(const float4*)&Ws[k][tx*8];
            *(float4*)&b[4] = *(const float4*)&Ws[k][tx*8 + 4];
            #pragma unroll
            for (int i = 0; i < 8; ++i)
                #pragma unroll
                for (int j = 0; j < 8; ++j) acc[i][j] += a[i]*b[j];
        }
        __syncthreads();
    }

    // Epilogue
    float bb[8];
    *(float4*)&bb[0] = *(const float4*)&bias[tx*8];
    *(float4*)&bb[4] = *(const float4*)&bias[tx*8 + 4];

    #pragma unroll
    for (int i = 0; i < 8; ++i) {
        const size_t r = (size_t)(row0 + ty*8 + i);
        float v[8];
        #pragma unroll
        for (int j = 0; j < 8; ++j) {
            float t = acc[i][j] + bb[j];
            if (ACT) t = lrelu(t);
            v[j] = t;
        }
        if (RES) {
            float rr[8];
            *(float4*)&rr[0] = *(const float4*)&R[r*F_ + tx*8];
            *(float4*)&rr[4] = *(const float4*)&R[r*F_ + tx*8 + 4];
            #pragma unroll
            for (int j = 0; j < 8; ++j) v[j] += rr[j];
        }
        *(float4*)&Y[r*F_ + tx*8]     = *(float4*)&v[0];
        *(float4*)&Y[r*F_ + tx*8 + 4] = *(float4*)&v[4];
    }
}

// ---------------------------------------------------------------------------
// Split-K partials of S[b] = w2[b]^T @ x[b].
// grid = (NSPLIT_, B_); each block reduces a 128-row K chunk -> Spart[b][split].
// ---------------------------------------------------------------------------
__global__ void __launch_bounds__(256) calc_S(
    const float* __restrict__ w2, const float* __restrict__ x,
    float* __restrict__ Spart)
{
    const int split = blockIdx.x;
    const int b     = blockIdx.y;
    const int k0    = b*N_ + split*128;   // absolute row offset

    __shared__ float As[32][128];   // w2 chunk [k][m]
    __shared__ float Bs[32][128];   // x  chunk [k][n]

    const int tid = threadIdx.x;
    const int tx  = tid & 15;
    const int ty  = tid >> 4;

    float acc[8][8];
    #pragma unroll
    for (int i = 0; i < 8; ++i)
        #pragma unroll
        for (int j = 0; j < 8; ++j) acc[i][j] = 0.f;

    for (int c = 0; c < 4; ++c) {
        #pragma unroll
        for (int i = 0; i < 4; ++i) {
            int f4 = tid + i*256;
            int r  = f4 >> 5;
            int q  = (f4 & 31) << 2;
            size_t g = (size_t)(k0 + c*32 + r)*F_ + q;
            *(float4*)&As[r][q] = *(const float4*)&w2[g];
            *(float4*)&Bs[r][q] = *(const float4*)&x[g];
        }
        __syncthreads();

        #pragma unroll
        for (int k = 0; k < 32; ++k) {
            float a[8], bv[8];
            *(float4*)&a[0]  = *(const float4*)&As[k][ty*8];
            *(float4*)&a[4]  = *(const float4*)&As[k][ty*8 + 4];
            *(float4*)&bv[0] = *(const float4*)&Bs[k][tx*8];
            *(float4*)&bv[4] = *(const float4*)&Bs[k][tx*8 + 4];
            #pragma unroll
            for (int i = 0; i < 8; ++i)
                #pragma unroll
                for (int j = 0; j < 8; ++j) acc[i][j] += a[i]*bv[j];
        }
        __syncthreads();
    }

    float* out = Spart + ((size_t)b*NSPLIT_ + split)*F_*F_;
    #pragma unroll
    for (int i = 0; i < 8; ++i) {
        #pragma unroll
        for (int j = 0; j < 8; j += 4) {
            float4 v = make_float4(acc[i][j], acc[i][j+1], acc[i][j+2], acc[i][j+3]);
            *(float4*)&out[(size_t)(ty*8 + i)*F_ + tx*8 + j] = v;
        }
    }
}

// Deterministic reduction of split-K partials: S[b] = sum_s Spart[b][s]
__global__ void __launch_bounds__(256) reduce_S(
    const float* __restrict__ Sp, float* __restrict__ S)
{
    int idx = blockIdx.x*256 + threadIdx.x;      // 0 .. B_*F_*F_-1
    int b   = idx >> 14;                          // / (128*128)
    int ij  = idx & 16383;
    const float* p = Sp + (size_t)b*NSPLIT_*F_*F_ + ij;
    float s = 0.f;
    #pragma unroll
    for (int t = 0; t < NSPLIT_; ++t) s += p[(size_t)t*F_*F_];
    S[idx] = s;
}

// ---------------------------------------------------------------------------
// msg = (w1 @ S[b] - diag .* x) / (N-1),  diag_i = w1_i . w2_i
// 64-row tiles, 256 threads, 4x8 register tile per thread.
// ---------------------------------------------------------------------------
__global__ void __launch_bounds__(256) calc_msg(
    const float* __restrict__ w1, const float* __restrict__ w2,
    const float* __restrict__ x,  const float* __restrict__ S,
    float* __restrict__ msg)
{
    const int row0 = blockIdx.x * 64;
    const int b    = row0 >> 11;                 // / N_
    const float* Sb = S + (size_t)b*F_*F_;

    __shared__ float w1s[64][33];
    __shared__ float Ss[32][128];
    __shared__ float diagS[64];

    const int tid = threadIdx.x;
    const int tx  = tid & 15;
    const int ty  = tid >> 4;

    // Phase 0: diag (4 threads per row)
    {
        int r = tid >> 2;
        int q = tid & 3;
        const float* p1 = w1 + (size_t)(row0 + r)*F_ + q*32;
        const float* p2 = w2 + (size_t)(row0 + r)*F_ + q*32;
        float s = 0.f;
        #pragma unroll
        for (int j = 0; j < 32; ++j) s += p1[j]*p2[j];
        s += __shfl_xor_sync(0xffffffffu, s, 1);
        s += __shfl_xor_sync(0xffffffffu, s, 2);
        if (q == 0) diagS[r] = s;
    }
    __syncthreads();

    float acc[4][8];
    #pragma unroll
    for (int i = 0; i < 4; ++i)
        #pragma unroll
        for (int j = 0; j < 8; ++j) acc[i][j] = 0.f;

    for (int c = 0; c < 4; ++c) {
        // w1 chunk: 64 x 32  (512 float4, 2 per thread)
        #pragma unroll
        for (int i = 0; i < 2; ++i) {
            int f4 = tid + i*256;
            int r  = f4 >> 3;
            int kq = (f4 & 7) << 2;
            float4 v = *(const float4*)&w1[(size_t)(row0 + r)*F_ + c*32 + kq];
            w1s[r][kq+0] = v.x; w1s[r][kq+1] = v.y; w1s[r][kq+2] = v.z; w1s[r][kq+3] = v.w;
        }
        // S chunk: 32 x 128
        #pragma unroll
        for (int i = 0; i < 4; ++i) {
            int f4 = tid + i*256;
            int r  = f4 >> 5;
            int q  = (f4 & 31) << 2;
            *(float4*)&Ss[r][q] = *(const float4*)&Sb[(size_t)(c*32 + r)*F_ + q];
        }
        __syncthreads();

        #pragma unroll
        for (int k = 0; k < 32; ++k) {
            float a[4], bv[8];
            #pragma unroll
            for (int i = 0; i < 4; ++i) a[i] = w1s[ty*4 + i][k];
            *(float4*)&bv[0] = *(const float4*)&Ss[k][tx*8];
            *(float4*)&bv[4] = *(const float4*)&Ss[k][tx*8 + 4];
            #pragma unroll
            for (int i = 0; i < 4; ++i)
                #pragma unroll
                for (int j = 0; j < 8; ++j) acc[i][j] += a[i]*bv[j];
        }
        __syncthreads();
    }

    // Epilogue: msg = (acc - diag*x) * INV_NM1
    #pragma unroll
    for (int i = 0; i < 4; ++i) {
        const int m = ty*4 + i;
        const size_t r = (size_t)(row0 + m);
        const float d = diagS[m];
        float xv[8];
        *(float4*)&xv[0] = *(const float4*)&x[r*F_ + tx*8];
        *(float4*)&xv[4] = *(const float4*)&x[r*F_ + tx*8 + 4];
        float v[8];
        #pragma unroll
        for (int j = 0; j < 8; ++j)
            v[j] = (acc[i][j] - d*xv[j]) * INV_NM1_;
        *(float4*)&msg[r*F_ + tx*8]     = *(float4*)&v[0];
        *(float4*)&msg[r*F_ + tx*8 + 4] = *(float4*)&v[4];
    }
}

// ---------------------------------------------------------------------------
extern "C" void kernel_launch(void* const* d_in, const int* in_sizes, int n_in,
                              void* d_out, int out_size)
{
    const float* x  = (const float*)d_in[0];
    const float* W3 = (const float*)d_in[1];
    const float* b3 = (const float*)d_in[2];
    const float* W4 = (const float*)d_in[3];
    const float* b4 = (const float*)d_in[4];
    const float* W5 = (const float*)d_in[5];
    const float* b5 = (const float*)d_in[6];
    float* out = (float*)d_out;

    float *pw1, *pw2, *pmsg, *pSp, *pS;
    cudaGetSymbolAddress((void**)&pw1,  g_w1);
    cudaGetSymbolAddress((void**)&pw2,  g_w2);
    cudaGetSymbolAddress((void**)&pmsg, g_msg);
    cudaGetSymbolAddress((void**)&pSp,  g_Spart);
    cudaGetSymbolAddress((void**)&pS,   g_S);

    for (int l = 0; l < LAYERS_; ++l) {
        const float* xin = l ? out : x;
        const float* W3l = W3 + (size_t)l*F_*F_;
        const float* b3l = b3 + (size_t)l*F_;
        const float* W4l = W4 + (size_t)l*F_*F_;
        const float* b4l = b4 + (size_t)l*F_;
        const float* W5l = W5 + (size_t)l*F_*F_;
        const float* b5l = b5 + (size_t)l*F_;

        // w1 = lrelu(x@W3 + b3),  w2 = lrelu(x@W4 + b4)
        gemm128<true,false><<<M_/128, 256>>>(xin, W3l, b3l, nullptr, pw1);
        gemm128<true,false><<<M_/128, 256>>>(xin, W4l, b4l, nullptr, pw2);

        // S[b] = w2[b]^T @ x[b]  (split-K + deterministic reduce)
        calc_S<<<dim3(NSPLIT_, B_), 256>>>(pw2, xin, pSp);
        reduce_S<<<(B_*F_*F_)/256, 256>>>(pSp, pS);

        // msg = (w1@S - diag.*x)/(N-1)
        calc_msg<<<M_/64, 256>>>(pw1, pw2, xin, pS, pmsg);

        // out = lrelu(msg@W5 + b5) + x
        gemm128<true,true><<<M_/128, 256>>>(pmsg, W5l, b5l, xin, out);
    }
}

// round 3
// speedup vs baseline: 1.2308x; 1.2308x over previous
#include <cuda_runtime.h>

// Problem constants
#define B_ 8
#define N_ 2048
#define F_ 128
#define M_ (B_*N_)          // 16384 total rows
#define LAYERS_ 2
#define NSPLIT_ 16          // split-K for S reduction
#define SLOPE_ 0.1f
#define INV_NM1_ (1.0f/2047.0f)

typedef unsigned long long ull;

// Scratch (device globals; no cudaMalloc allowed)
__device__ float g_w1[M_*F_];
__device__ float g_w2[M_*F_];
__device__ float g_msg[M_*F_];
__device__ float g_Spart[B_*NSPLIT_*F_*F_];
__device__ float g_S[B_*F_*F_];

__device__ __forceinline__ float lrelu(float v) { return v >= 0.f ? v : SLOPE_*v; }

// ---- packed fp32x2 helpers (sm_100+: single FFMA2 issue = 2 FMAs) ----
__device__ __forceinline__ ull dup2(float a) {
    ull r; asm("mov.b64 %0, {%1, %1};" : "=l"(r) : "f"(a)); return r;
}
__device__ __forceinline__ ull ffma2(ull a, ull b, ull c) {
    ull d; asm("fma.rn.f32x2 %0, %1, %2, %3;" : "=l"(d) : "l"(a), "l"(b), "l"(c));
    return d;
}
__device__ __forceinline__ float2 unpk(ull v) {
    float2 f; asm("mov.b64 {%0, %1}, %2;" : "=f"(f.x), "=f"(f.y) : "l"(v)); return f;
}

// ---------------------------------------------------------------------------
// Core 128x128x128 f32x2 MAC tile. Xs[row][k] padded, Ws[k][col].
// 256 threads: tx = tid&15 (8 cols), ty = tid>>4 (8 rows). acc2[8][4] packed j.
// ---------------------------------------------------------------------------
struct TileCtx { int tx, ty; };

__device__ __forceinline__ void mac_chunk(
    const float (*Xs)[33], const float (*Ws)[128],
    int tx, int ty, ull acc2[8][4])
{
    #pragma unroll
    for (int k = 0; k < 32; ++k) {
        ull b2[4];
        {
            ulonglong2 t0 = *(const ulonglong2*)&Ws[k][tx*8];
            ulonglong2 t1 = *(const ulonglong2*)&Ws[k][tx*8 + 4];
            b2[0] = t0.x; b2[1] = t0.y; b2[2] = t1.x; b2[3] = t1.y;
        }
        #pragma unroll
        for (int i = 0; i < 8; ++i) {
            ull a2 = dup2(Xs[ty*8 + i][k]);
            #pragma unroll
            for (int j = 0; j < 4; ++j) acc2[i][j] = ffma2(a2, b2[j], acc2[i][j]);
        }
    }
}

__device__ __forceinline__ void load_X_chunk(
    const float* __restrict__ X, int row0, int c, int tid, float (*Xs)[33])
{
    #pragma unroll
    for (int i = 0; i < 4; ++i) {
        int f4 = tid + i*256;
        int r  = f4 >> 3;
        int kq = (f4 & 7) << 2;
        float4 v = *(const float4*)&X[(size_t)(row0 + r)*F_ + c*32 + kq];
        Xs[r][kq+0] = v.x; Xs[r][kq+1] = v.y; Xs[r][kq+2] = v.z; Xs[r][kq+3] = v.w;
    }
}

__device__ __forceinline__ void load_W_chunk(
    const float* __restrict__ W, int c, int tid, float (*Ws)[128])
{
    #pragma unroll
    for (int i = 0; i < 4; ++i) {
        int f4 = tid + i*256;
        int r  = f4 >> 5;
        int q  = (f4 & 31) << 2;
        *(float4*)&Ws[r][q] = *(const float4*)&W[(size_t)(c*32 + r)*F_ + q];
    }
}

// ---------------------------------------------------------------------------
// Fused: w1 = lrelu(x@W3+b3), w2 = lrelu(x@W4+b4). 256 blocks, sel by high bit.
// ---------------------------------------------------------------------------
__global__ void __launch_bounds__(256) gemm_w1w2(
    const float* __restrict__ X,
    const float* __restrict__ W3, const float* __restrict__ b3,
    const float* __restrict__ W4, const float* __restrict__ b4,
    float* __restrict__ Y1, float* __restrict__ Y2)
{
    __shared__ float Xs[128][33];
    __shared__ float Ws[32][128];

    const int sel  = blockIdx.x >> 7;
    const int row0 = (blockIdx.x & 127) * 128;
    const float* W    = sel ? W4 : W3;
    const float* bias = sel ? b4 : b3;
    float*       Y    = sel ? Y2 : Y1;

    const int tid = threadIdx.x;
    const int tx  = tid & 15;
    const int ty  = tid >> 4;

    ull acc2[8][4];
    #pragma unroll
    for (int i = 0; i < 8; ++i)
        #pragma unroll
        for (int j = 0; j < 4; ++j) acc2[i][j] = 0ull;

    for (int c = 0; c < 4; ++c) {
        load_X_chunk(X, row0, c, tid, Xs);
        load_W_chunk(W, c, tid, Ws);
        __syncthreads();
        mac_chunk(Xs, Ws, tx, ty, acc2);
        __syncthreads();
    }

    float bb[8];
    *(float4*)&bb[0] = *(const float4*)&bias[tx*8];
    *(float4*)&bb[4] = *(const float4*)&bias[tx*8 + 4];

    #pragma unroll
    for (int i = 0; i < 8; ++i) {
        const size_t r = (size_t)(row0 + ty*8 + i);
        float v[8];
        #pragma unroll
        for (int j = 0; j < 4; ++j) {
            float2 f = unpk(acc2[i][j]);
            v[2*j] = f.x; v[2*j+1] = f.y;
        }
        #pragma unroll
        for (int j = 0; j < 8; ++j) v[j] = lrelu(v[j] + bb[j]);
        *(float4*)&Y[r*F_ + tx*8]     = *(float4*)&v[0];
        *(float4*)&Y[r*F_ + tx*8 + 4] = *(float4*)&v[4];
    }
}

// ---------------------------------------------------------------------------
// out = lrelu(X@W + b) + R
// ---------------------------------------------------------------------------
__global__ void __launch_bounds__(256) gemm_out(
    const float* __restrict__ X, const float* __restrict__ W,
    const float* __restrict__ bias, const float* __restrict__ R,
    float* __restrict__ Y)
{
    __shared__ float Xs[128][33];
    __shared__ float Ws[32][128];

    const int row0 = blockIdx.x * 128;
    const int tid  = threadIdx.x;
    const int tx   = tid & 15;
    const int ty   = tid >> 4;

    ull acc2[8][4];
    #pragma unroll
    for (int i = 0; i < 8; ++i)
        #pragma unroll
        for (int j = 0; j < 4; ++j) acc2[i][j] = 0ull;

    for (int c = 0; c < 4; ++c) {
        load_X_chunk(X, row0, c, tid, Xs);
        load_W_chunk(W, c, tid, Ws);
        __syncthreads();
        mac_chunk(Xs, Ws, tx, ty, acc2);
        __syncthreads();
    }

    float bb[8];
    *(float4*)&bb[0] = *(const float4*)&bias[tx*8];
    *(float4*)&bb[4] = *(const float4*)&bias[tx*8 + 4];

    #pragma unroll
    for (int i = 0; i < 8; ++i) {
        const size_t r = (size_t)(row0 + ty*8 + i);
        float v[8], rr[8];
        #pragma unroll
        for (int j = 0; j < 4; ++j) {
            float2 f = unpk(acc2[i][j]);
            v[2*j] = f.x; v[2*j+1] = f.y;
        }
        *(float4*)&rr[0] = *(const float4*)&R[r*F_ + tx*8];
        *(float4*)&rr[4] = *(const float4*)&R[r*F_ + tx*8 + 4];
        #pragma unroll
        for (int j = 0; j < 8; ++j) v[j] = lrelu(v[j] + bb[j]) + rr[j];
        *(float4*)&Y[r*F_ + tx*8]     = *(float4*)&v[0];
        *(float4*)&Y[r*F_ + tx*8 + 4] = *(float4*)&v[4];
    }
}

// ---------------------------------------------------------------------------
// Split-K partials of S[b] = w2[b]^T @ x[b]. grid = (NSPLIT_, B_).
// ---------------------------------------------------------------------------
__global__ void __launch_bounds__(256) calc_S(
    const float* __restrict__ w2, const float* __restrict__ x,
    float* __restrict__ Spart)
{
    const int split = blockIdx.x;
    const int b     = blockIdx.y;
    const int k0    = b*N_ + split*128;

    __shared__ float As[32][128];
    __shared__ float Bs[32][128];

    const int tid = threadIdx.x;
    const int tx  = tid & 15;
    const int ty  = tid >> 4;

    ull acc2[8][4];
    #pragma unroll
    for (int i = 0; i < 8; ++i)
        #pragma unroll
        for (int j = 0; j < 4; ++j) acc2[i][j] = 0ull;

    for (int c = 0; c < 4; ++c) {
        #pragma unroll
        for (int i = 0; i < 4; ++i) {
            int f4 = tid + i*256;
            int r  = f4 >> 5;
            int q  = (f4 & 31) << 2;
            size_t g = (size_t)(k0 + c*32 + r)*F_ + q;
            *(float4*)&As[r][q] = *(const float4*)&w2[g];
            *(float4*)&Bs[r][q] = *(const float4*)&x[g];
        }
        __syncthreads();

        #pragma unroll
        for (int k = 0; k < 32; ++k) {
            ull b2[4];
            {
                ulonglong2 t0 = *(const ulonglong2*)&Bs[k][tx*8];
                ulonglong2 t1 = *(const ulonglong2*)&Bs[k][tx*8 + 4];
                b2[0] = t0.x; b2[1] = t0.y; b2[2] = t1.x; b2[3] = t1.y;
            }
            float a[8];
            *(float4*)&a[0] = *(const float4*)&As[k][ty*8];
            *(float4*)&a[4] = *(const float4*)&As[k][ty*8 + 4];
            #pragma unroll
            for (int i = 0; i < 8; ++i) {
                ull a2 = dup2(a[i]);
                #pragma unroll
                for (int j = 0; j < 4; ++j) acc2[i][j] = ffma2(a2, b2[j], acc2[i][j]);
            }
        }
        __syncthreads();
    }

    float* out = Spart + ((size_t)b*NSPLIT_ + split)*F_*F_;
    #pragma unroll
    for (int i = 0; i < 8; ++i) {
        float v[8];
        #pragma unroll
        for (int j = 0; j < 4; ++j) {
            float2 f = unpk(acc2[i][j]);
            v[2*j] = f.x; v[2*j+1] = f.y;
        }
        *(float4*)&out[(size_t)(ty*8 + i)*F_ + tx*8]     = *(float4*)&v[0];
        *(float4*)&out[(size_t)(ty*8 + i)*F_ + tx*8 + 4] = *(float4*)&v[4];
    }
}

// Deterministic float4 reduction of split-K partials
__global__ void __launch_bounds__(256) reduce_S(
    const float4* __restrict__ Sp, float4* __restrict__ S)
{
    int idx = blockIdx.x*256 + threadIdx.x;      // per-float4, B_*F_*F_/4 total
    int b   = idx >> 12;                          // 4096 float4 per batch
    int ij  = idx & 4095;
    const float4* p = Sp + (size_t)b*NSPLIT_*4096 + ij;
    float4 s = p[0];
    #pragma unroll
    for (int t = 1; t < NSPLIT_; ++t) {
        float4 v = p[(size_t)t*4096];
        s.x += v.x; s.y += v.y; s.z += v.z; s.w += v.w;
    }
    S[idx] = s;
}

// ---------------------------------------------------------------------------
// msg = (w1 @ S[b] - diag .* x) / (N-1),  diag_i = w1_i . w2_i. 128-row tiles.
// ---------------------------------------------------------------------------
__global__ void __launch_bounds__(256) calc_msg(
    const float* __restrict__ w1, const float* __restrict__ w2,
    const float* __restrict__ x,  const float* __restrict__ S,
    float* __restrict__ msg)
{
    const int row0 = blockIdx.x * 128;
    const int b    = row0 >> 11;
    const float* Sb = S + (size_t)b*F_*F_;

    __shared__ float w1s[128][33];
    __shared__ float Ss[32][128];
    __shared__ float diagS[128];

    const int tid = threadIdx.x;
    const int tx  = tid & 15;
    const int ty  = tid >> 4;

    // diag: 2 threads per row, 64 elements each
    {
        int r = tid >> 1;
        int q = tid & 1;
        const float* p1 = w1 + (size_t)(row0 + r)*F_ + q*64;
        const float* p2 = w2 + (size_t)(row0 + r)*F_ + q*64;
        float s = 0.f;
        #pragma unroll
        for (int j = 0; j < 16; ++j) {
            float4 u = *(const float4*)&p1[j*4];
            float4 v = *(const float4*)&p2[j*4];
            s += u.x*v.x + u.y*v.y + u.z*v.z + u.w*v.w;
        }
        s += __shfl_xor_sync(0xffffffffu, s, 1);
        if (q == 0) diagS[r] = s;
    }
    __syncthreads();

    ull acc2[8][4];
    #pragma unroll
    for (int i = 0; i < 8; ++i)
        #pragma unroll
        for (int j = 0; j < 4; ++j) acc2[i][j] = 0ull;

    for (int c = 0; c < 4; ++c) {
        load_X_chunk(w1, row0, c, tid, w1s);
        load_W_chunk(Sb, c, tid, Ss);
        __syncthreads();
        mac_chunk(w1s, Ss, tx, ty, acc2);
        __syncthreads();
    }

    #pragma unroll
    for (int i = 0; i < 8; ++i) {
        const int m = ty*8 + i;
        const size_t r = (size_t)(row0 + m);
        const float d = diagS[m];
        float xv[8], v[8];
        *(float4*)&xv[0] = *(const float4*)&x[r*F_ + tx*8];
        *(float4*)&xv[4] = *(const float4*)&x[r*F_ + tx*8 + 4];
        #pragma unroll
        for (int j = 0; j < 4; ++j) {
            float2 f = unpk(acc2[i][j]);
            v[2*j] = f.x; v[2*j+1] = f.y;
        }
        #pragma unroll
        for (int j = 0; j < 8; ++j)
            v[j] = (v[j] - d*xv[j]) * INV_NM1_;
        *(float4*)&msg[r*F_ + tx*8]     = *(float4*)&v[0];
        *(float4*)&msg[r*F_ + tx*8 + 4] = *(float4*)&v[4];
    }
}

// ---------------------------------------------------------------------------
extern "C" void kernel_launch(void* const* d_in, const int* in_sizes, int n_in,
                              void* d_out, int out_size)
{
    const float* x  = (const float*)d_in[0];
    const float* W3 = (const float*)d_in[1];
    const float* b3 = (const float*)d_in[2];
    const float* W4 = (const float*)d_in[3];
    const float* b4 = (const float*)d_in[4];
    const float* W5 = (const float*)d_in[5];
    const float* b5 = (const float*)d_in[6];
    float* out = (float*)d_out;

    float *pw1, *pw2, *pmsg, *pSp, *pS;
    cudaGetSymbolAddress((void**)&pw1,  g_w1);
    cudaGetSymbolAddress((void**)&pw2,  g_w2);
    cudaGetSymbolAddress((void**)&pmsg, g_msg);
    cudaGetSymbolAddress((void**)&pSp,  g_Spart);
    cudaGetSymbolAddress((void**)&pS,   g_S);

    for (int l = 0; l < LAYERS_; ++l) {
        const float* xin = l ? out : x;
        const float* W3l = W3 + (size_t)l*F_*F_;
        const float* b3l = b3 + (size_t)l*F_;
        const float* W4l = W4 + (size_t)l*F_*F_;
        const float* b4l = b4 + (size_t)l*F_;
        const float* W5l = W5 + (size_t)l*F_*F_;
        const float* b5l = b5 + (size_t)l*F_;

        gemm_w1w2<<<256, 256>>>(xin, W3l, b3l, W4l, b4l, pw1, pw2);
        calc_S<<<dim3(NSPLIT_, B_), 256>>>(pw2, xin, pSp);
        reduce_S<<<(B_*F_*F_)/(4*256), 256>>>((const float4*)pSp, (float4*)pS);
        calc_msg<<<M_/128, 256>>>(pw1, pw2, xin, pS, pmsg);
        gemm_out<<<M_/128, 256>>>(pmsg, W5l, b5l, xin, out);
    }
}

// round 5
// speedup vs baseline: 1.3028x; 1.0585x over previous
#include <cuda_runtime.h>

// Problem constants
#define B_ 8
#define N_ 2048
#define F_ 128
#define M_ (B_*N_)          // 16384 total rows
#define LAYERS_ 2
#define NSPLIT_ 16
#define SLOPE_ 0.1f
#define INV_NM1_ (1.0f/2047.0f)
#define PADT_ 132           // XsT row pad: 132*4 bytes = multiple of 16 (float4-safe)

typedef unsigned long long ull;

// Scratch (device globals; no cudaMalloc allowed)
__device__ float g_w1[M_*F_];
__device__ float g_w2[M_*F_];
__device__ float g_diag[M_];
__device__ float g_Spart[B_*NSPLIT_*F_*F_];
__device__ float g_S[B_*F_*F_];

__device__ __forceinline__ float lrelu(float v) { return v >= 0.f ? v : SLOPE_*v; }

// ---- packed fp32x2 helpers (sm_100+: one FFMA2 issue = 2 FMAs) ----
__device__ __forceinline__ ull dup2(float a) {
    ull r; asm("mov.b64 %0, {%1, %1};" : "=l"(r) : "f"(a)); return r;
}
__device__ __forceinline__ ull ffma2(ull a, ull b, ull c) {
    ull d; asm("fma.rn.f32x2 %0, %1, %2, %3;" : "=l"(d) : "l"(a), "l"(b), "l"(c));
    return d;
}
__device__ __forceinline__ float2 unpk(ull v) {
    float2 f; asm("mov.b64 {%0, %1}, %2;" : "=f"(f.x), "=f"(f.y) : "l"(v)); return f;
}

// ---------------------------------------------------------------------------
// Shared tile helpers. A transposed: XsT[k][row] (pad PADT_). B: Ws[k][col].
// 256 threads: tx = tid&15 (8 cols), ty = tid>>4 (8 rows).
// ---------------------------------------------------------------------------
__device__ __forceinline__ void load_XT_chunk(
    const float* __restrict__ X, int row0, int c, int tid, float (*XsT)[PADT_])
{
    #pragma unroll
    for (int i = 0; i < 4; ++i) {
        int f4 = tid + i*256;
        int r  = f4 >> 3;             // 0..127
        int kq = (f4 & 7) << 2;       // 0..28
        float4 v = *(const float4*)&X[(size_t)(row0 + r)*F_ + c*32 + kq];
        XsT[kq+0][r] = v.x; XsT[kq+1][r] = v.y;
        XsT[kq+2][r] = v.z; XsT[kq+3][r] = v.w;
    }
}

__device__ __forceinline__ void load_W_chunk(
    const float* __restrict__ W, int c, int tid, float (*Ws)[128])
{
    #pragma unroll
    for (int i = 0; i < 4; ++i) {
        int f4 = tid + i*256;
        int r  = f4 >> 5;
        int q  = (f4 & 31) << 2;
        *(float4*)&Ws[r][q] = *(const float4*)&W[(size_t)(c*32 + r)*F_ + q];
    }
}

__device__ __forceinline__ void mac_chunk_T(
    const float (*XsT)[PADT_], const float (*Ws)[128],
    int tx, int ty, ull acc2[8][4])
{
    #pragma unroll
    for (int k = 0; k < 32; ++k) {
        float a[8];
        *(float4*)&a[0] = *(const float4*)&XsT[k][ty*8];
        *(float4*)&a[4] = *(const float4*)&XsT[k][ty*8 + 4];
        ull b2[4];
        {
            ulonglong2 t0 = *(const ulonglong2*)&Ws[k][tx*8];
            ulonglong2 t1 = *(const ulonglong2*)&Ws[k][tx*8 + 4];
            b2[0] = t0.x; b2[1] = t0.y; b2[2] = t1.x; b2[3] = t1.y;
        }
        #pragma unroll
        for (int i = 0; i < 8; ++i) {
            ull a2 = dup2(a[i]);
            #pragma unroll
            for (int j = 0; j < 4; ++j) acc2[i][j] = ffma2(a2, b2[j], acc2[i][j]);
        }
    }
}

__device__ __forceinline__ void zero_acc(ull acc2[8][4]) {
    #pragma unroll
    for (int i = 0; i < 8; ++i)
        #pragma unroll
        for (int j = 0; j < 4; ++j) acc2[i][j] = 0ull;
}

// ---------------------------------------------------------------------------
// Fused: w1 = lrelu(x@W3+b3), w2 = lrelu(x@W4+b4), diag_i = w1_i . w2_i.
// ---------------------------------------------------------------------------
__global__ void __launch_bounds__(256) k_w1w2(
    const float* __restrict__ X,
    const float* __restrict__ W3, const float* __restrict__ b3,
    const float* __restrict__ W4, const float* __restrict__ b4,
    float* __restrict__ Y1, float* __restrict__ Y2, float* __restrict__ diag)
{
    __shared__ float XsT[32][PADT_];
    __shared__ float Ws[32][128];

    const int row0 = blockIdx.x * 128;
    const int tid  = threadIdx.x;
    const int tx   = tid & 15;
    const int ty   = tid >> 4;

    ull acc2[8][4];
    zero_acc(acc2);

    // ---- stage A: w1 ----
    for (int c = 0; c < 4; ++c) {
        load_XT_chunk(X, row0, c, tid, XsT);
        load_W_chunk(W3, c, tid, Ws);
        __syncthreads();
        mac_chunk_T(XsT, Ws, tx, ty, acc2);
        __syncthreads();
    }

    float w1v[8][8];
    {
        float bb[8];
        *(float4*)&bb[0] = *(const float4*)&b3[tx*8];
        *(float4*)&bb[4] = *(const float4*)&b3[tx*8 + 4];
        #pragma unroll
        for (int i = 0; i < 8; ++i) {
            const size_t r = (size_t)(row0 + ty*8 + i);
            #pragma unroll
            for (int j = 0; j < 4; ++j) {
                float2 f = unpk(acc2[i][j]);
                w1v[i][2*j]   = lrelu(f.x + bb[2*j]);
                w1v[i][2*j+1] = lrelu(f.y + bb[2*j+1]);
            }
            *(float4*)&Y1[r*F_ + tx*8]     = *(float4*)&w1v[i][0];
            *(float4*)&Y1[r*F_ + tx*8 + 4] = *(float4*)&w1v[i][4];
        }
    }

    // ---- stage B: w2 + diag ----
    zero_acc(acc2);
    for (int c = 0; c < 4; ++c) {
        load_XT_chunk(X, row0, c, tid, XsT);
        load_W_chunk(W4, c, tid, Ws);
        __syncthreads();
        mac_chunk_T(XsT, Ws, tx, ty, acc2);
        __syncthreads();
    }

    {
        float bb[8];
        *(float4*)&bb[0] = *(const float4*)&b4[tx*8];
        *(float4*)&bb[4] = *(const float4*)&b4[tx*8 + 4];
        #pragma unroll
        for (int i = 0; i < 8; ++i) {
            const size_t r = (size_t)(row0 + ty*8 + i);
            float v[8];
            #pragma unroll
            for (int j = 0; j < 4; ++j) {
                float2 f = unpk(acc2[i][j]);
                v[2*j]   = lrelu(f.x + bb[2*j]);
                v[2*j+1] = lrelu(f.y + bb[2*j+1]);
            }
            *(float4*)&Y2[r*F_ + tx*8]     = *(float4*)&v[0];
            *(float4*)&Y2[r*F_ + tx*8 + 4] = *(float4*)&v[4];
            float d = 0.f;
            #pragma unroll
            for (int j = 0; j < 8; ++j) d += w1v[i][j] * v[j];
            d += __shfl_xor_sync(0xffffffffu, d, 1);
            d += __shfl_xor_sync(0xffffffffu, d, 2);
            d += __shfl_xor_sync(0xffffffffu, d, 4);
            d += __shfl_xor_sync(0xffffffffu, d, 8);
            if (tx == 0) diag[r] = d;
        }
    }
}

// ---------------------------------------------------------------------------
// Split-K partials of S[b] = w2[b]^T @ x[b]. grid = (NSPLIT_, B_).
// ---------------------------------------------------------------------------
__global__ void __launch_bounds__(256) calc_S(
    const float* __restrict__ w2, const float* __restrict__ x,
    float* __restrict__ Spart)
{
    const int split = blockIdx.x;
    const int b     = blockIdx.y;
    const int k0    = b*N_ + split*128;

    __shared__ float As[32][128];
    __shared__ float Bs[32][128];

    const int tid = threadIdx.x;
    const int tx  = tid & 15;
    const int ty  = tid >> 4;

    ull acc2[8][4];
    zero_acc(acc2);

    for (int c = 0; c < 4; ++c) {
        #pragma unroll
        for (int i = 0; i < 4; ++i) {
            int f4 = tid + i*256;
            int r  = f4 >> 5;
            int q  = (f4 & 31) << 2;
            size_t g = (size_t)(k0 + c*32 + r)*F_ + q;
            *(float4*)&As[r][q] = *(const float4*)&w2[g];
            *(float4*)&Bs[r][q] = *(const float4*)&x[g];
        }
        __syncthreads();

        #pragma unroll
        for (int k = 0; k < 32; ++k) {
            float a[8];
            *(float4*)&a[0] = *(const float4*)&As[k][ty*8];
            *(float4*)&a[4] = *(const float4*)&As[k][ty*8 + 4];
            ull b2[4];
            {
                ulonglong2 t0 = *(const ulonglong2*)&Bs[k][tx*8];
                ulonglong2 t1 = *(const ulonglong2*)&Bs[k][tx*8 + 4];
                b2[0] = t0.x; b2[1] = t0.y; b2[2] = t1.x; b2[3] = t1.y;
            }
            #pragma unroll
            for (int i = 0; i < 8; ++i) {
                ull a2 = dup2(a[i]);
                #pragma unroll
                for (int j = 0; j < 4; ++j) acc2[i][j] = ffma2(a2, b2[j], acc2[i][j]);
            }
        }
        __syncthreads();
    }

    float* out = Spart + ((size_t)b*NSPLIT_ + split)*F_*F_;
    #pragma unroll
    for (int i = 0; i < 8; ++i) {
        float v[8];
        #pragma unroll
        for (int j = 0; j < 4; ++j) {
            float2 f = unpk(acc2[i][j]);
            v[2*j] = f.x; v[2*j+1] = f.y;
        }
        *(float4*)&out[(size_t)(ty*8 + i)*F_ + tx*8]     = *(float4*)&v[0];
        *(float4*)&out[(size_t)(ty*8 + i)*F_ + tx*8 + 4] = *(float4*)&v[4];
    }
}

// Deterministic float4 reduction of split-K partials
__global__ void __launch_bounds__(256) reduce_S(
    const float4* __restrict__ Sp, float4* __restrict__ S)
{
    int idx = blockIdx.x*256 + threadIdx.x;
    int b   = idx >> 12;
    int ij  = idx & 4095;
    const float4* p = Sp + (size_t)b*NSPLIT_*4096 + ij;
    float4 s = p[0];
    #pragma unroll
    for (int t = 1; t < NSPLIT_; ++t) {
        float4 v = p[(size_t)t*4096];
        s.x += v.x; s.y += v.y; s.z += v.z; s.w += v.w;
    }
    S[idx] = s;
}

// ---------------------------------------------------------------------------
// Fused: msg = (w1@S[b] - diag.*x)/(N-1), then out = lrelu(msg@W5+b5) + x.
// msg lives in registers between stages; staged chunkwise into XsT for GEMM2.
// ---------------------------------------------------------------------------
__global__ void __launch_bounds__(256) k_msg_out(
    const float* __restrict__ w1, const float* __restrict__ diag,
    const float* __restrict__ x,  const float* __restrict__ S,
    const float* __restrict__ W5, const float* __restrict__ b5,
    float* __restrict__ out)
{
    const int row0 = blockIdx.x * 128;
    const int b    = row0 >> 11;
    const float* Sb = S + (size_t)b*F_*F_;

    __shared__ float XsT[32][PADT_];
    __shared__ float Ws[32][128];
    __shared__ float dsh[128];

    const int tid = threadIdx.x;
    const int tx  = tid & 15;
    const int ty  = tid >> 4;

    if (tid < 128) dsh[tid] = diag[row0 + tid];

    ull acc2[8][4];
    zero_acc(acc2);

    // ---- stage 1: acc = w1 @ Sb ----
    for (int c = 0; c < 4; ++c) {
        load_XT_chunk(w1, row0, c, tid, XsT);
        load_W_chunk(Sb, c, tid, Ws);
        __syncthreads();
        mac_chunk_T(XsT, Ws, tx, ty, acc2);
        __syncthreads();
    }

    // msg values in registers
    float msgv[8][8];
    #pragma unroll
    for (int i = 0; i < 8; ++i) {
        const int m = ty*8 + i;
        const size_t r = (size_t)(row0 + m);
        const float d = dsh[m];
        float xv[8];
        *(float4*)&xv[0] = *(const float4*)&x[r*F_ + tx*8];
        *(float4*)&xv[4] = *(const float4*)&x[r*F_ + tx*8 + 4];
        #pragma unroll
        for (int j = 0; j < 4; ++j) {
            float2 f = unpk(acc2[i][j]);
            msgv[i][2*j]   = (f.x - d*xv[2*j])   * INV_NM1_;
            msgv[i][2*j+1] = (f.y - d*xv[2*j+1]) * INV_NM1_;
        }
    }

    // ---- stage 2: out = lrelu(msg @ W5 + b5) + x ----
    zero_acc(acc2);
    for (int c = 0; c < 4; ++c) {
        // threads owning cols of this k-chunk write msg^T into XsT
        if ((tx >> 2) == c) {
            #pragma unroll
            for (int jj = 0; jj < 8; ++jj) {
                int kk = (tx & 3)*8 + jj;
                #pragma unroll
                for (int i = 0; i < 8; ++i)
                    XsT[kk][ty*8 + i] = msgv[i][jj];
            }
        }
        load_W_chunk(W5, c, tid, Ws);
        __syncthreads();
        mac_chunk_T(XsT, Ws, tx, ty, acc2);
        __syncthreads();
    }

    {
        float bb[8];
        *(float4*)&bb[0] = *(const float4*)&b5[tx*8];
        *(float4*)&bb[4] = *(const float4*)&b5[tx*8 + 4];
        #pragma unroll
        for (int i = 0; i < 8; ++i) {
            const size_t r = (size_t)(row0 + ty*8 + i);
            float xv[8], v[8];
            *(float4*)&xv[0] = *(const float4*)&x[r*F_ + tx*8];
            *(float4*)&xv[4] = *(const float4*)&x[r*F_ + tx*8 + 4];
            #pragma unroll
            for (int j = 0; j < 4; ++j) {
                float2 f = unpk(acc2[i][j]);
                v[2*j]   = lrelu(f.x + bb[2*j])   + xv[2*j];
                v[2*j+1] = lrelu(f.y + bb[2*j+1]) + xv[2*j+1];
            }
            *(float4*)&out[r*F_ + tx*8]     = *(float4*)&v[0];
            *(float4*)&out[r*F_ + tx*8 + 4] = *(float4*)&v[4];
        }
    }
}

// ---------------------------------------------------------------------------
extern "C" void kernel_launch(void* const* d_in, const int* in_sizes, int n_in,
                              void* d_out, int out_size)
{
    const float* x  = (const float*)d_in[0];
    const float* W3 = (const float*)d_in[1];
    const float* b3 = (const float*)d_in[2];
    const float* W4 = (const float*)d_in[3];
    const float* b4 = (const float*)d_in[4];
    const float* W5 = (const float*)d_in[5];
    const float* b5 = (const float*)d_in[6];
    float* out = (float*)d_out;

    float *pw1, *pw2, *pdg, *pSp, *pS;
    cudaGetSymbolAddress((void**)&pw1, g_w1);
    cudaGetSymbolAddress((void**)&pw2, g_w2);
    cudaGetSymbolAddress((void**)&pdg, g_diag);
    cudaGetSymbolAddress((void**)&pSp, g_Spart);
    cudaGetSymbolAddress((void**)&pS,  g_S);

    for (int l = 0; l < LAYERS_; ++l) {
        const float* xin = l ? out : x;
        const float* W3l = W3 + (size_t)l*F_*F_;
        const float* b3l = b3 + (size_t)l*F_;
        const float* W4l = W4 + (size_t)l*F_*F_;
        const float* b4l = b4 + (size_t)l*F_;
        const float* W5l = W5 + (size_t)l*F_*F_;
        const float* b5l = b5 + (size_t)l*F_;

        k_w1w2<<<M_/128, 256>>>(xin, W3l, b3l, W4l, b4l, pw1, pw2, pdg);
        calc_S<<<dim3(NSPLIT_, B_), 256>>>(pw2, xin, pSp);
        reduce_S<<<(B_*F_*F_)/(4*256), 256>>>((const float4*)pSp, (float4*)pS);
        k_msg_out<<<M_/128, 256>>>(pw1, pdg, xin, pS, W5l, b5l, out);
    }
}